// round 5
// baseline (speedup 1.0000x reference)
#include <cuda_runtime.h>
#include <math.h>
#include <stdint.h>

#define T_LEN 512
#define BATCH 64
#define ISZ   256
#define HID   512
#define GH    2048   // 4*HID, gate order f,i,o,c
#define NCTA  128

// ---------------- device scratch (no allocations allowed) ----------------
__device__ float g_gx[(size_t)T_LEN * GH * BATCH];  // [t][n=g*512+h][b]
__device__ float g_h[2][HID * BATCH];               // double-buffered h, [h][b]
__device__ volatile unsigned g_flags[NCTA];         // per-CTA step counters

// ---------------- packed f32x2 helpers (sm_100+) ----------------
union F2U { float2 f; unsigned long long u; };
__device__ __forceinline__ float2 ffma2(float2 a, float2 b, float2 c) {
    F2U A, B, C, D; A.f = a; B.f = b; C.f = c;
    asm("fma.rn.f32x2 %0, %1, %2, %3;" : "=l"(D.u) : "l"(A.u), "l"(B.u), "l"(C.u));
    return D.f;
}
__device__ __forceinline__ float2 fadd2(float2 a, float2 b) {
    F2U A, B, D; A.f = a; B.f = b;
    asm("add.rn.f32x2 %0, %1, %2;" : "=l"(D.u) : "l"(A.u), "l"(B.u));
    return D.f;
}
__device__ __forceinline__ float fast_sigmoid(float x) {
    return __fdividef(1.0f, 1.0f + __expf(-x));
}
__device__ __forceinline__ float fast_tanh(float x) {
    return __fdividef(2.0f, 1.0f + __expf(-2.0f * x)) - 1.0f;
}

// ---------------- init: zero h buffers + flags each replay ----------------
__global__ void init_state_kernel() {
    int idx = blockIdx.x * blockDim.x + threadIdx.x;
    if (idx < 2 * HID * BATCH) ((float*)g_h)[idx] = 0.0f;
    if (idx < NCTA) g_flags[idx] = 0u;
}

// ---------------- gx = x @ Wx^T + bx  -> g_gx[t][n][b] ----------------
__global__ __launch_bounds__(256) void gx_kernel(const float* __restrict__ x,
                                                 const float* __restrict__ Wx,
                                                 const float* __restrict__ bx) {
    extern __shared__ float sm[];
    float* x_s = sm;               // [256][65] padded transpose
    float* Ws  = sm + 256 * 65;    // [32][256]
    const int tid = threadIdx.x;
    const int t   = blockIdx.y;
    const int n0  = blockIdx.x * 32;

    const float* xt = x + (size_t)t * BATCH * ISZ;
    #pragma unroll 4
    for (int r = 0; r < 64; r++) {
        int idx = r * 256 + tid;
        int b = idx >> 8;
        int i = idx & 255;
        x_s[i * 65 + b] = xt[idx];
    }
    const float* Wrow = Wx + (size_t)n0 * ISZ;
    #pragma unroll 4
    for (int r = 0; r < 32; r++) {
        int idx = r * 256 + tid;
        Ws[idx] = Wrow[idx];
    }
    __syncthreads();

    const int b  = tid & 63;
    const int ng = tid >> 6;
    float acc[8];
    #pragma unroll
    for (int j = 0; j < 8; j++) acc[j] = 0.0f;

    const float4* Ws4 = (const float4*)(Ws + (ng * 8) * ISZ);
    #pragma unroll 2
    for (int k4 = 0; k4 < 64; k4++) {
        const int k = k4 * 4;
        const float xa = x_s[(k + 0) * 65 + b];
        const float xb = x_s[(k + 1) * 65 + b];
        const float xc = x_s[(k + 2) * 65 + b];
        const float xd = x_s[(k + 3) * 65 + b];
        #pragma unroll
        for (int j = 0; j < 8; j++) {
            float4 w = Ws4[j * 64 + k4];
            acc[j] += w.x * xa;
            acc[j] += w.y * xb;
            acc[j] += w.z * xc;
            acc[j] += w.w * xd;
        }
    }

    const size_t base = ((size_t)t * GH + n0 + ng * 8) * BATCH + b;
    #pragma unroll
    for (int j = 0; j < 8; j++) {
        g_gx[base + (size_t)j * BATCH] = acc[j] + __ldg(&bx[n0 + ng * 8 + j]);
    }
}

// ---------------- persistent recurrence kernel ----------------
// 128 CTAs (1/SM) x 256 threads. CTA owns 4 hidden units h0..h0+3 (16 W rows).
// GEMM tiling: out[16 rows][64 b] = Wt[512 k][16 r]^T-style x hs[512 k][64 b].
// Thread = (warp, lane) with lane = (ksub:1, rg:1, bg:3):
//   k-slice s = warp*2 + ksub (16 slices x 32 k), rows rg*8..rg*8+7,
//   batch f2-pairs {bg, bg+8, bg+16, bg+24}.
// Per k: 2x LDS.128 unique W + 4x LDS.64 h = 64 B for 64 MACs (32 FFMA2).
// K-partials reduced via smem; epilogue threads own cells (c in registers).
__global__ __launch_bounds__(256) void lstm_persistent(
        const float* __restrict__ Wh,
        const float* __restrict__ bh,
        float* __restrict__ h_seq,
        float* __restrict__ out_hlast,
        float* __restrict__ out_clast) {
    extern __shared__ float sm[];
    float*  Wt  = sm;                        // [512 k][16 r]  (32 KB)
    float*  hs  = sm + 512 * 16;             // [512 k][64 b]  (128 KB)
    float2* red = (float2*)(hs + HID * BATCH); // [16 r][32 bp][16 s] f2 (64 KB)

    const int tid  = threadIdx.x;
    const int lane = tid & 31;
    const int warp = tid >> 5;
    const int bg   = lane & 7;
    const int rg   = (lane >> 3) & 1;
    const int ksub = lane >> 4;
    const int s    = warp * 2 + ksub;        // k-slice 0..15
    const int bid  = blockIdx.x;
    const int h0   = bid * 4;

    // ---- stage Wt once: Wt[k][r] = Wh[(g*HID + h0 + hl)][k], r = g*4+hl
    for (int it = 0; it < 32; it++) {
        int idx = it * 256 + tid;            // 0..8191 = r*512 + k
        int r = idx >> 9, k = idx & 511;
        int g = r >> 2, hl = r & 3;
        Wt[k * 16 + r] = Wh[((size_t)(g * HID + h0 + hl)) * HID + k];
    }

    // epilogue threads: tid < 128, cell = (hl = tid>>5, bp = tid&31)
    const bool epi = (tid < 128);
    const int ehl = tid >> 5;
    const int ebp = tid & 31;
    const int eh  = h0 + ehl;
    float bhf = 0.f, bhi = 0.f, bho = 0.f, bhc = 0.f;
    if (epi) {
        bhf = __ldg(&bh[0 * HID + eh]);
        bhi = __ldg(&bh[1 * HID + eh]);
        bho = __ldg(&bh[2 * HID + eh]);
        bhc = __ldg(&bh[3 * HID + eh]);
    }
    float c0 = 0.0f, c1 = 0.0f;

    __syncthreads();

    int cur = 0;
    for (int t = 0; t < T_LEN; t++) {
        // ---- gx prefetch (constant inputs, issue before the flag wait)
        float2 gx0, gx1, gx2, gx3;
        if (epi) {
            const float* gp = g_gx + ((size_t)t * GH + eh) * BATCH + 2 * ebp;
            gx0 = __ldg((const float2*)(gp + (size_t)0 * HID * BATCH));
            gx1 = __ldg((const float2*)(gp + (size_t)1 * HID * BATCH));
            gx2 = __ldg((const float2*)(gp + (size_t)2 * HID * BATCH));
            gx3 = __ldg((const float2*)(gp + (size_t)3 * HID * BATCH));
        }

        // ---- wait: all CTAs have published h for step t
        if (t > 0) {
            if (tid < NCTA) {
                while (g_flags[tid] < (unsigned)t) { __nanosleep(32); }
            }
            __syncthreads();
        }

        // ---- stage h: global (st.cg-written, L2) -> smem via cp.async.cg
        {
            const float4* src = (const float4*)g_h[cur];
            uint32_t dbase = (uint32_t)__cvta_generic_to_shared(hs);
            #pragma unroll 8
            for (int it = 0; it < 32; it++) {
                int idx = it * 256 + tid;
                uint32_t d = dbase + idx * 16;
                asm volatile("cp.async.cg.shared.global [%0], [%1], 16;"
                             :: "r"(d), "l"(src + idx));
            }
            asm volatile("cp.async.commit_group;");
            asm volatile("cp.async.wait_group 0;");
        }
        __syncthreads();

        // ---- GEMM microkernel: 8 rows x 4 f2-batches over 32 k's
        float2 acc[8][4];
        #pragma unroll
        for (int ri = 0; ri < 8; ri++)
            #pragma unroll
            for (int j = 0; j < 4; j++) acc[ri][j] = make_float2(0.f, 0.f);

        const float* wp = Wt + (s * 32) * 16 + rg * 8;
        const float* hp = hs + (s * 32) * 64 + 2 * bg;

        #pragma unroll 4
        for (int kl = 0; kl < 32; kl++) {
            const float4 wa = *(const float4*)(wp);
            const float4 wb = *(const float4*)(wp + 4);
            const float2 hv0 = *(const float2*)(hp + 0);
            const float2 hv1 = *(const float2*)(hp + 16);
            const float2 hv2 = *(const float2*)(hp + 32);
            const float2 hv3 = *(const float2*)(hp + 48);
            float ws[8] = {wa.x, wa.y, wa.z, wa.w, wb.x, wb.y, wb.z, wb.w};
            #pragma unroll
            for (int ri = 0; ri < 8; ri++) {
                const float2 wd = make_float2(ws[ri], ws[ri]);
                acc[ri][0] = ffma2(hv0, wd, acc[ri][0]);
                acc[ri][1] = ffma2(hv1, wd, acc[ri][1]);
                acc[ri][2] = ffma2(hv2, wd, acc[ri][2]);
                acc[ri][3] = ffma2(hv3, wd, acc[ri][3]);
            }
            wp += 16;
            hp += 64;
        }

        // ---- scatter partials: red[r][bp][s]
        {
            float2* rp = red + (((size_t)(rg * 8) * 32 + bg) * 16) + s;
            #pragma unroll
            for (int ri = 0; ri < 8; ri++)
                #pragma unroll
                for (int j = 0; j < 4; j++)
                    rp[ri * 512 + j * 128] = acc[ri][j];
        }
        __syncthreads();

        // ---- reduce + gates (cell threads)
        if (epi) {
            float2 gsum[4];
            #pragma unroll
            for (int g = 0; g < 4; g++) {
                const float4* q = (const float4*)(red + ((size_t)((g * 4 + ehl) * 32 + ebp)) * 16);
                float2 sum = make_float2(0.f, 0.f);
                #pragma unroll
                for (int m = 0; m < 8; m++) {
                    float4 v = q[m];
                    sum = fadd2(sum, make_float2(v.x, v.y));
                    sum = fadd2(sum, make_float2(v.z, v.w));
                }
                gsum[g] = sum;
            }

            const float pf0 = gsum[0].x + gx0.x + bhf, pf1 = gsum[0].y + gx0.y + bhf;
            const float pi0 = gsum[1].x + gx1.x + bhi, pi1 = gsum[1].y + gx1.y + bhi;
            const float po0 = gsum[2].x + gx2.x + bho, po1 = gsum[2].y + gx2.y + bho;
            const float pc0 = gsum[3].x + gx3.x + bhc, pc1 = gsum[3].y + gx3.y + bhc;

            const float f0 = fast_sigmoid(pf0), f1 = fast_sigmoid(pf1);
            const float i0 = fast_sigmoid(pi0), i1 = fast_sigmoid(pi1);
            const float o0 = fast_sigmoid(po0), o1 = fast_sigmoid(po1);
            const float q0 = fast_tanh(pc0),    q1 = fast_tanh(pc1);

            c0 = f0 * c0 + i0 * q0;
            c1 = f1 * c1 + i1 * q1;
            const float hn0 = o0 * fast_tanh(c0);
            const float hn1 = o1 * fast_tanh(c1);

            __stcg((float2*)(g_h[cur ^ 1] + eh * BATCH + 2 * ebp),
                   make_float2(hn0, hn1));

            float* so = h_seq + ((size_t)t * BATCH + 2 * ebp) * HID + eh;
            so[0]   = hn0;
            so[HID] = hn1;
            if (t == T_LEN - 1) {
                out_hlast[(size_t)(2 * ebp) * HID + eh]     = hn0;
                out_hlast[(size_t)(2 * ebp + 1) * HID + eh] = hn1;
                out_clast[(size_t)(2 * ebp) * HID + eh]     = c0;
                out_clast[(size_t)(2 * ebp + 1) * HID + eh] = c1;
            }
            __threadfence();
        }

        // ---- release
        __syncthreads();
        if (tid == 0) g_flags[bid] = (unsigned)(t + 1);
        cur ^= 1;
    }
}

// ---------------- launch ----------------
extern "C" void kernel_launch(void* const* d_in, const int* in_sizes, int n_in,
                              void* d_out, int out_size) {
    const float* x  = (const float*)d_in[0];
    const float* Wx = (const float*)d_in[1];
    const float* bx = (const float*)d_in[2];
    const float* Wh = (const float*)d_in[3];
    const float* bh = (const float*)d_in[4];

    float* out       = (float*)d_out;
    float* out_hlast = out + (size_t)T_LEN * BATCH * HID;
    float* out_clast = out_hlast + (size_t)BATCH * HID;

    const int gx_smem = (256 * 65 + 32 * 256) * sizeof(float);   // 99328 B
    const int ps_smem = (512 * 16 + HID * BATCH + 16 * 32 * 16 * 2) * sizeof(float); // 229376 B
    cudaFuncSetAttribute(gx_kernel,       cudaFuncAttributeMaxDynamicSharedMemorySize, gx_smem);
    cudaFuncSetAttribute(lstm_persistent, cudaFuncAttributeMaxDynamicSharedMemorySize, ps_smem);

    init_state_kernel<<<128, 512>>>();
    gx_kernel<<<dim3(64, 512), 256, gx_smem>>>(x, Wx, bx);
    lstm_persistent<<<NCTA, 256, ps_smem>>>(Wh, bh, out, out_hlast, out_clast);
}

// round 6
// speedup vs baseline: 1.9308x; 1.9308x over previous
#include <cuda_runtime.h>
#include <math.h>
#include <stdint.h>

#define T_LEN 512
#define BATCH 64
#define ISZ   256
#define HID   512
#define GH    2048   // 4*HID, gate order f,i,o,c
#define NCTA  128

// ---------------- device scratch (no allocations allowed) ----------------
__device__ float g_gx[(size_t)T_LEN * GH * BATCH];  // [t][n=g*512+h][b] (bx+bh folded in)
__device__ float g_h[2][HID * BATCH];               // double-buffered h, [h][b]
__device__ unsigned g_bar;                          // barrier arrival counter
__device__ volatile unsigned g_epoch;               // barrier release epoch

// ---------------- packed f32x2 helpers (sm_100+) ----------------
union F2U { float2 f; unsigned long long u; };
__device__ __forceinline__ float2 ffma2(float2 a, float2 b, float2 c) {
    F2U A, B, C, D; A.f = a; B.f = b; C.f = c;
    asm("fma.rn.f32x2 %0, %1, %2, %3;" : "=l"(D.u) : "l"(A.u), "l"(B.u), "l"(C.u));
    return D.f;
}
__device__ __forceinline__ float2 fadd2(float2 a, float2 b) {
    F2U A, B, D; A.f = a; B.f = b;
    asm("add.rn.f32x2 %0, %1, %2;" : "=l"(D.u) : "l"(A.u), "l"(B.u));
    return D.f;
}
__device__ __forceinline__ float fast_sigmoid(float x) {
    return __fdividef(1.0f, 1.0f + __expf(-x));
}
__device__ __forceinline__ float fast_tanh(float x) {
    return __fdividef(2.0f, 1.0f + __expf(-2.0f * x)) - 1.0f;
}

// ---------------- mbarrier helpers ----------------
__device__ __forceinline__ unsigned smem_u32(const void* p) {
    return (unsigned)__cvta_generic_to_shared(p);
}
__device__ __forceinline__ void mbar_init(unsigned bar, unsigned count) {
    asm volatile("mbarrier.init.shared.b64 [%0], %1;" :: "r"(bar), "r"(count) : "memory");
}
__device__ __forceinline__ void mbar_expect_tx(unsigned bar, unsigned bytes) {
    asm volatile("mbarrier.arrive.expect_tx.shared.b64 _, [%0], %1;"
                 :: "r"(bar), "r"(bytes) : "memory");
}
__device__ __forceinline__ void bulk_g2s(unsigned dst, const void* src, unsigned bytes, unsigned bar) {
    asm volatile("cp.async.bulk.shared::cta.global.mbarrier::complete_tx::bytes [%0], [%1], %2, [%3];"
                 :: "r"(dst), "l"(src), "r"(bytes), "r"(bar) : "memory");
}
__device__ __forceinline__ void mbar_wait(unsigned bar, unsigned parity) {
    asm volatile(
        "{\n\t"
        ".reg .pred P;\n\t"
        "WAIT_%=:\n\t"
        "mbarrier.try_wait.parity.acquire.cta.shared::cta.b64 P, [%0], %1;\n\t"
        "@!P bra WAIT_%=;\n\t"
        "}"
        :: "r"(bar), "r"(parity) : "memory");
}

// ---------------- init: zero h buffers + barrier state ----------------
__global__ void init_state_kernel() {
    int idx = blockIdx.x * blockDim.x + threadIdx.x;
    if (idx < 2 * HID * BATCH) ((float*)g_h)[idx] = 0.0f;
    if (idx == 0) { g_bar = 0; g_epoch = 0; }
}

// ---------------- gx = x @ Wx^T + (bx + bh)  -> g_gx[t][n][b] ----------------
__global__ __launch_bounds__(256) void gx_kernel(const float* __restrict__ x,
                                                 const float* __restrict__ Wx,
                                                 const float* __restrict__ bx,
                                                 const float* __restrict__ bh) {
    extern __shared__ float sm[];
    float* x_s = sm;               // [256][65] padded transpose
    float* Ws  = sm + 256 * 65;    // [32][256]
    const int tid = threadIdx.x;
    const int t   = blockIdx.y;
    const int n0  = blockIdx.x * 32;

    const float* xt = x + (size_t)t * BATCH * ISZ;
    #pragma unroll 4
    for (int r = 0; r < 64; r++) {
        int idx = r * 256 + tid;
        int b = idx >> 8;
        int i = idx & 255;
        x_s[i * 65 + b] = xt[idx];
    }
    const float* Wrow = Wx + (size_t)n0 * ISZ;
    #pragma unroll 4
    for (int r = 0; r < 32; r++) {
        int idx = r * 256 + tid;
        Ws[idx] = Wrow[idx];
    }
    __syncthreads();

    const int b  = tid & 63;
    const int ng = tid >> 6;
    float acc[8];
    #pragma unroll
    for (int j = 0; j < 8; j++) acc[j] = 0.0f;

    const float4* Ws4 = (const float4*)(Ws + (ng * 8) * ISZ);
    #pragma unroll 2
    for (int k4 = 0; k4 < 64; k4++) {
        const int k = k4 * 4;
        const float xa = x_s[(k + 0) * 65 + b];
        const float xb = x_s[(k + 1) * 65 + b];
        const float xc = x_s[(k + 2) * 65 + b];
        const float xd = x_s[(k + 3) * 65 + b];
        #pragma unroll
        for (int j = 0; j < 8; j++) {
            float4 w = Ws4[j * 64 + k4];
            acc[j] += w.x * xa;
            acc[j] += w.y * xb;
            acc[j] += w.z * xc;
            acc[j] += w.w * xd;
        }
    }

    const size_t base = ((size_t)t * GH + n0 + ng * 8) * BATCH + b;
    #pragma unroll
    for (int j = 0; j < 8; j++) {
        const int n = n0 + ng * 8 + j;
        g_gx[base + (size_t)j * BATCH] = acc[j] + __ldg(&bx[n]) + __ldg(&bh[n]);
    }
}

// ---------------- persistent recurrence kernel ----------------
// 128 CTAs (1/SM) x 256 threads (8 warps). CTA owns 4 hidden units (16 rows).
// Wsp smem layout: [k][hl][g] so a warp's rows are contiguous and gate-pairs
// pack as f2 -> W loads are plain LDS.128 broadcasts (no duplication).
// Warp (khq, hlh): k-quarter khq (128 k), hl in {2hlh, 2hlh+1}, all 64 batches.
// Lane bp: batches (2bp, 2bp+1). h duplicated in registers (2 MOV/k).
// h staged per step via 4x cp.async.bulk 32KB chunks; warp waits only its chunk.
__global__ __launch_bounds__(256, 1) void lstm_persistent(
        const float* __restrict__ Wh,
        float* __restrict__ h_seq,
        float* __restrict__ out_hlast,
        float* __restrict__ out_clast) {
    extern __shared__ float sm[];
    float*  Wsp  = sm;                      // [512 k][16 r(hl,g)]  32 KB
    float*  hs   = sm + 8192;               // [512 k][64 b]       128 KB
    float2* red  = (float2*)(sm + 8192 + 32768);  // 2048 f2        16 KB
    float*  tile = sm + 8192 + 32768 + 4096;      // [4 hl][64 b]    1 KB
    unsigned long long* mbar = (unsigned long long*)(tile + 256);  // 4 barriers

    const int tid  = threadIdx.x;
    const int bp   = tid & 31;
    const int warp = tid >> 5;
    const int hlh  = warp & 1;
    const int khq  = warp >> 1;
    const int bid  = blockIdx.x;
    const int h0   = bid * 4;

    // ---- stage Wsp once: Wsp[k*16 + hl*4 + g] = Wh[g*512 + h0 + hl][k]
    #pragma unroll
    for (int it = 0; it < 32; it++) {
        int idx = it * 256 + tid;            // 0..8191 = r*512 + k
        int r = idx >> 9, k = idx & 511;
        int hl = r >> 2, g = r & 3;
        Wsp[k * 16 + hl * 4 + g] = Wh[((size_t)(g * HID + h0 + hl)) * HID + k];
    }
    if (tid == 0) {
        #pragma unroll
        for (int q = 0; q < 4; q++) mbar_init(smem_u32(&mbar[q]), 1);
    }

    // epilogue threads: tid < 128 -> cell (ehl = tid>>5, ebp = tid&31)
    const bool epi = (tid < 128);
    const int ehl = tid >> 5;
    const int ebp = tid & 31;
    const int eh  = h0 + ehl;
    float c0 = 0.0f, c1 = 0.0f;

    const unsigned my_bar = smem_u32(&mbar[khq]);
    const unsigned hs_dst0 = smem_u32(hs);

    __syncthreads();

    int cur = 0;
    for (int t = 0; t < T_LEN; t++) {
        // ---- gx prefetch (h-independent; overlaps the flag wait)
        float2 gxf, gxi, gxo, gxc;
        if (epi) {
            const float* gp = g_gx + ((size_t)t * GH + eh) * BATCH + 2 * ebp;
            gxf = __ldg((const float2*)(gp + (size_t)0 * HID * BATCH));
            gxi = __ldg((const float2*)(gp + (size_t)1 * HID * BATCH));
            gxo = __ldg((const float2*)(gp + (size_t)2 * HID * BATCH));
            gxc = __ldg((const float2*)(gp + (size_t)3 * HID * BATCH));
        }

        // ---- tid0: wait for all CTAs' h(t-1), then kick 4 bulk copies
        if (tid == 0) {
            if (t > 0) {
                while (g_epoch < (unsigned)t) { __nanosleep(64); }
            }
            const char* src = (const char*)g_h[cur];
            #pragma unroll
            for (int q = 0; q < 4; q++) {
                unsigned bq = smem_u32(&mbar[q]);
                mbar_expect_tx(bq, 32768u);
                bulk_g2s(hs_dst0 + q * 32768u, src + q * 32768u, 32768u, bq);
            }
        }

        // ---- wait only for this warp's k-quarter
        mbar_wait(my_bar, (unsigned)(t & 1));

        // ---- compute: 128 k x (2 hl rows x 2 gate-pairs x 2 batches)
        float2 A000 = make_float2(0.f, 0.f), A001 = A000, A010 = A000, A011 = A000;
        float2 A100 = A000, A101 = A000, A110 = A000, A111 = A000;

        const float* wP = Wsp + (khq * 128) * 16 + 8 * hlh;
        const float* hP = hs + (khq * 128) * 64 + 2 * bp;

        #pragma unroll 4
        for (int kl = 0; kl < 128; kl++) {
            const float4 w4a = *(const float4*)(wP);       // rows: hl=2hlh, gates 0..3
            const float4 w4b = *(const float4*)(wP + 4);   // rows: hl=2hlh+1
            const float2 hv  = *(const float2*)(hP);
            const float2 d0 = make_float2(hv.x, hv.x);
            const float2 d1 = make_float2(hv.y, hv.y);
            const float2 w01a = make_float2(w4a.x, w4a.y);
            const float2 w23a = make_float2(w4a.z, w4a.w);
            const float2 w01b = make_float2(w4b.x, w4b.y);
            const float2 w23b = make_float2(w4b.z, w4b.w);
            A000 = ffma2(w01a, d0, A000);
            A001 = ffma2(w01a, d1, A001);
            A010 = ffma2(w23a, d0, A010);
            A011 = ffma2(w23a, d1, A011);
            A100 = ffma2(w01b, d0, A100);
            A101 = ffma2(w01b, d1, A101);
            A110 = ffma2(w23b, d0, A110);
            A111 = ffma2(w23b, d1, A111);
            wP += 16;
            hP += 64;
        }

        // ---- scatter partials: red[((khq*4+hl)*2+gp)*64 + b] (f2 = gate pair)
        {
            const int hlA = 2 * hlh, hlB = 2 * hlh + 1;
            float4* r0 = (float4*)(red + ((khq * 4 + hlA) * 2 + 0) * 64 + 2 * bp);
            float4* r1 = (float4*)(red + ((khq * 4 + hlA) * 2 + 1) * 64 + 2 * bp);
            float4* r2 = (float4*)(red + ((khq * 4 + hlB) * 2 + 0) * 64 + 2 * bp);
            float4* r3 = (float4*)(red + ((khq * 4 + hlB) * 2 + 1) * 64 + 2 * bp);
            *r0 = make_float4(A000.x, A000.y, A001.x, A001.y);
            *r1 = make_float4(A010.x, A010.y, A011.x, A011.y);
            *r2 = make_float4(A100.x, A100.y, A101.x, A101.y);
            *r3 = make_float4(A110.x, A110.y, A111.x, A111.y);
        }
        __syncthreads();

        // ---- reduce 4 k-quarters + gates (epi threads)
        if (epi) {
            float2 s01_0 = make_float2(0.f, 0.f), s01_1 = s01_0;
            float2 s23_0 = s01_0, s23_1 = s01_0;
            #pragma unroll
            for (int q = 0; q < 4; q++) {
                const float4 v01 = *(const float4*)(red + ((q * 4 + ehl) * 2 + 0) * 64 + 2 * ebp);
                const float4 v23 = *(const float4*)(red + ((q * 4 + ehl) * 2 + 1) * 64 + 2 * ebp);
                s01_0 = fadd2(s01_0, make_float2(v01.x, v01.y));
                s01_1 = fadd2(s01_1, make_float2(v01.z, v01.w));
                s23_0 = fadd2(s23_0, make_float2(v23.x, v23.y));
                s23_1 = fadd2(s23_1, make_float2(v23.z, v23.w));
            }
            // s01 = (f, i), s23 = (o, c); gx already contains bx + bh
            const float pf0 = s01_0.x + gxf.x, pf1 = s01_1.x + gxf.y;
            const float pi0 = s01_0.y + gxi.x, pi1 = s01_1.y + gxi.y;
            const float po0 = s23_0.x + gxo.x, po1 = s23_1.x + gxo.y;
            const float pc0 = s23_0.y + gxc.x, pc1 = s23_1.y + gxc.y;

            const float f0 = fast_sigmoid(pf0), f1 = fast_sigmoid(pf1);
            const float i0 = fast_sigmoid(pi0), i1 = fast_sigmoid(pi1);
            const float o0 = fast_sigmoid(po0), o1 = fast_sigmoid(po1);
            const float q0 = fast_tanh(pc0),    q1 = fast_tanh(pc1);

            c0 = f0 * c0 + i0 * q0;
            c1 = f1 * c1 + i1 * q1;
            const float hn0 = o0 * fast_tanh(c0);
            const float hn1 = o1 * fast_tanh(c1);

            __stcg((float2*)(g_h[cur ^ 1] + eh * BATCH + 2 * ebp),
                   make_float2(hn0, hn1));
            *(float2*)(tile + ehl * 64 + 2 * ebp) = make_float2(hn0, hn1);

            if (t == T_LEN - 1) {
                out_hlast[(size_t)(2 * ebp) * HID + eh]     = hn0;
                out_hlast[(size_t)(2 * ebp + 1) * HID + eh] = hn1;
                out_clast[(size_t)(2 * ebp) * HID + eh]     = c0;
                out_clast[(size_t)(2 * ebp + 1) * HID + eh] = c1;
            }
        }
        __syncthreads();

        // ---- release ASAP (h stores fenced; h_seq write happens after, off-path)
        if (tid == 0) {
            __threadfence();
            unsigned old = atomicAdd(&g_bar, 1u);
            if (old == (unsigned)t * NCTA + (NCTA - 1)) {
                g_epoch = (unsigned)(t + 1);
            }
        }

        // ---- h_seq[t][b][h0..h0+3] coalesced from tile (warps 6,7)
        if (warp >= 6) {
            const int b = tid - 192;   // 0..63
            float4 v = make_float4(tile[0 * 64 + b], tile[1 * 64 + b],
                                   tile[2 * 64 + b], tile[3 * 64 + b]);
            *(float4*)&h_seq[((size_t)t * BATCH + b) * HID + h0] = v;
        }

        cur ^= 1;
    }
}

// ---------------- launch ----------------
extern "C" void kernel_launch(void* const* d_in, const int* in_sizes, int n_in,
                              void* d_out, int out_size) {
    const float* x  = (const float*)d_in[0];
    const float* Wx = (const float*)d_in[1];
    const float* bx = (const float*)d_in[2];
    const float* Wh = (const float*)d_in[3];
    const float* bh = (const float*)d_in[4];

    float* out       = (float*)d_out;
    float* out_hlast = out + (size_t)T_LEN * BATCH * HID;
    float* out_clast = out_hlast + (size_t)BATCH * HID;

    const int gx_smem = (256 * 65 + 32 * 256) * sizeof(float);   // 99328 B
    const int ps_smem = (8192 + 32768 + 4096 + 256 + 16) * sizeof(float); // 181312 B
    cudaFuncSetAttribute(gx_kernel,       cudaFuncAttributeMaxDynamicSharedMemorySize, gx_smem);
    cudaFuncSetAttribute(lstm_persistent, cudaFuncAttributeMaxDynamicSharedMemorySize, ps_smem);

    init_state_kernel<<<128, 512>>>();
    gx_kernel<<<dim3(64, 512), 256, gx_smem>>>(x, Wx, bx, bh);
    lstm_persistent<<<NCTA, 256, ps_smem>>>(Wh, out, out_hlast, out_clast);
}

// round 7
// speedup vs baseline: 1.9884x; 1.0298x over previous
#include <cuda_runtime.h>
#include <math.h>
#include <stdint.h>

#define T_LEN 512
#define BATCH 64
#define ISZ   256
#define HID   512
#define GH    2048   // 4*HID, gate order f,i,o,c
#define NCTA  128

// ---------------- device scratch (no allocations allowed) ----------------
__device__ float g_gx[(size_t)T_LEN * GH * BATCH];  // [t][n=g*512+h][b] (bx+bh folded in)
__device__ float g_h[2][HID * BATCH];               // double-buffered h, [h][b]
__device__ unsigned g_bars[4];                      // per-group arrival counters
__device__ volatile unsigned g_epochs[4];           // per-group release epochs

// ---------------- packed f32x2 helpers (sm_100+) ----------------
union F2U { float2 f; unsigned long long u; };
__device__ __forceinline__ float2 ffma2(float2 a, float2 b, float2 c) {
    F2U A, B, C, D; A.f = a; B.f = b; C.f = c;
    asm("fma.rn.f32x2 %0, %1, %2, %3;" : "=l"(D.u) : "l"(A.u), "l"(B.u), "l"(C.u));
    return D.f;
}
__device__ __forceinline__ float2 fadd2(float2 a, float2 b) {
    F2U A, B, D; A.f = a; B.f = b;
    asm("add.rn.f32x2 %0, %1, %2;" : "=l"(D.u) : "l"(A.u), "l"(B.u));
    return D.f;
}
__device__ __forceinline__ float fast_sigmoid(float x) {
    return __fdividef(1.0f, 1.0f + __expf(-x));
}
__device__ __forceinline__ float fast_tanh(float x) {
    return __fdividef(2.0f, 1.0f + __expf(-2.0f * x)) - 1.0f;
}

// ---------------- mbarrier helpers ----------------
__device__ __forceinline__ unsigned smem_u32(const void* p) {
    return (unsigned)__cvta_generic_to_shared(p);
}
__device__ __forceinline__ void mbar_init(unsigned bar, unsigned count) {
    asm volatile("mbarrier.init.shared.b64 [%0], %1;" :: "r"(bar), "r"(count) : "memory");
}
__device__ __forceinline__ void mbar_expect_tx(unsigned bar, unsigned bytes) {
    asm volatile("mbarrier.arrive.expect_tx.shared.b64 _, [%0], %1;"
                 :: "r"(bar), "r"(bytes) : "memory");
}
__device__ __forceinline__ void bulk_g2s(unsigned dst, const void* src, unsigned bytes, unsigned bar) {
    asm volatile("cp.async.bulk.shared::cta.global.mbarrier::complete_tx::bytes [%0], [%1], %2, [%3];"
                 :: "r"(dst), "l"(src), "r"(bytes), "r"(bar) : "memory");
}
__device__ __forceinline__ void mbar_wait(unsigned bar, unsigned parity) {
    asm volatile(
        "{\n\t"
        ".reg .pred P;\n\t"
        "WAIT_%=:\n\t"
        "mbarrier.try_wait.parity.acquire.cta.shared::cta.b64 P, [%0], %1;\n\t"
        "@!P bra WAIT_%=;\n\t"
        "}"
        :: "r"(bar), "r"(parity) : "memory");
}

// ---------------- init: zero h buffers + barrier state ----------------
__global__ void init_state_kernel() {
    int idx = blockIdx.x * blockDim.x + threadIdx.x;
    if (idx < 2 * HID * BATCH) ((float*)g_h)[idx] = 0.0f;
    if (idx < 4) { g_bars[idx] = 0; g_epochs[idx] = 0; }
}

// ---------------- gx = x @ Wx^T + (bx + bh)  -> g_gx[t][n][b] ----------------
__global__ __launch_bounds__(256) void gx_kernel(const float* __restrict__ x,
                                                 const float* __restrict__ Wx,
                                                 const float* __restrict__ bx,
                                                 const float* __restrict__ bh) {
    extern __shared__ float sm[];
    float* x_s = sm;               // [256][65] padded transpose
    float* Ws  = sm + 256 * 65;    // [32][256]
    const int tid = threadIdx.x;
    const int t   = blockIdx.y;
    const int n0  = blockIdx.x * 32;

    const float* xt = x + (size_t)t * BATCH * ISZ;
    #pragma unroll 4
    for (int r = 0; r < 64; r++) {
        int idx = r * 256 + tid;
        int b = idx >> 8;
        int i = idx & 255;
        x_s[i * 65 + b] = xt[idx];
    }
    const float* Wrow = Wx + (size_t)n0 * ISZ;
    #pragma unroll 4
    for (int r = 0; r < 32; r++) {
        int idx = r * 256 + tid;
        Ws[idx] = Wrow[idx];
    }
    __syncthreads();

    const int b  = tid & 63;
    const int ng = tid >> 6;
    float acc[8];
    #pragma unroll
    for (int j = 0; j < 8; j++) acc[j] = 0.0f;

    const float4* Ws4 = (const float4*)(Ws + (ng * 8) * ISZ);
    #pragma unroll 2
    for (int k4 = 0; k4 < 64; k4++) {
        const int k = k4 * 4;
        const float xa = x_s[(k + 0) * 65 + b];
        const float xb = x_s[(k + 1) * 65 + b];
        const float xc = x_s[(k + 2) * 65 + b];
        const float xd = x_s[(k + 3) * 65 + b];
        #pragma unroll
        for (int j = 0; j < 8; j++) {
            float4 w = Ws4[j * 64 + k4];
            acc[j] += w.x * xa;
            acc[j] += w.y * xb;
            acc[j] += w.z * xc;
            acc[j] += w.w * xd;
        }
    }

    const size_t base = ((size_t)t * GH + n0 + ng * 8) * BATCH + b;
    #pragma unroll
    for (int j = 0; j < 8; j++) {
        const int n = n0 + ng * 8 + j;
        g_gx[base + (size_t)j * BATCH] = acc[j] + __ldg(&bx[n]) + __ldg(&bh[n]);
    }
}

// ---------------- persistent recurrence kernel ----------------
// 128 CTAs (1/SM) x 256 threads (8 warps). CTA owns 4 hidden units (16 rows).
// h-quarter q (rows 128q..) is produced by CTA group q (bid in [32q, 32q+32)),
// tracked by g_epochs[q]: release->copy->compute pipelined per quarter.
// Warp (khq, hlh): k-quarter khq, hl pair hlh; lane bp = batch pair.
// Lane 0 of warp 2q stages quarter q (spin epoch[q], expect_tx, bulk copy).
__global__ __launch_bounds__(256, 1) void lstm_persistent(
        const float* __restrict__ Wh,
        float* __restrict__ h_seq,
        float* __restrict__ out_hlast,
        float* __restrict__ out_clast) {
    extern __shared__ float sm[];
    float*  Wsp  = sm;                      // [512 k][16 r(hl,g)]  32 KB
    float*  hs   = sm + 8192;               // [512 k][64 b]       128 KB
    float2* red  = (float2*)(sm + 8192 + 32768);  // 2048 f2        16 KB
    unsigned long long* mbar = (unsigned long long*)(sm + 8192 + 32768 + 4096);

    const int tid  = threadIdx.x;
    const int lane = tid & 31;
    const int warp = tid >> 5;
    const int bp   = lane;
    const int hlh  = warp & 1;
    const int khq  = warp >> 1;
    const int bid  = blockIdx.x;
    const int h0   = bid * 4;
    const int gid  = bid >> 5;              // this CTA's producer group
    const bool is_stager = (hlh == 0) && (lane == 0);   // lane 0 of warp 2q

    // ---- stage Wsp once: Wsp[k*16 + hl*4 + g] = Wh[g*512 + h0 + hl][k]
    #pragma unroll
    for (int it = 0; it < 32; it++) {
        int idx = it * 256 + tid;            // 0..8191 = r*512 + k
        int r = idx >> 9, k = idx & 511;
        int hl = r >> 2, g = r & 3;
        Wsp[k * 16 + hl * 4 + g] = Wh[((size_t)(g * HID + h0 + hl)) * HID + k];
    }
    if (tid == 0) {
        #pragma unroll
        for (int q = 0; q < 4; q++) mbar_init(smem_u32(&mbar[q]), 1);
    }

    // epilogue threads: tid < 128 -> cell (ehl = tid>>5, ebp = tid&31)
    const bool epi = (tid < 128);
    const int ehl = tid >> 5;
    const int ebp = tid & 31;
    const int eh  = h0 + ehl;
    float c0 = 0.0f, c1 = 0.0f;

    const unsigned my_bar  = smem_u32(&mbar[khq]);
    const unsigned hs_dst0 = smem_u32(hs);

    __syncthreads();

    int cur = 0;
    for (int t = 0; t < T_LEN; t++) {
        // ---- gx prefetch (h-independent; overlaps the epoch wait)
        float2 gxf, gxi, gxo, gxc;
        if (epi) {
            const float* gp = g_gx + ((size_t)t * GH + eh) * BATCH + 2 * ebp;
            gxf = __ldg((const float2*)(gp + (size_t)0 * HID * BATCH));
            gxi = __ldg((const float2*)(gp + (size_t)1 * HID * BATCH));
            gxo = __ldg((const float2*)(gp + (size_t)2 * HID * BATCH));
            gxc = __ldg((const float2*)(gp + (size_t)3 * HID * BATCH));
        }

        // ---- per-quarter stager: wait for its producer group, then copy
        if (is_stager) {
            if (t > 0) {
                while (g_epochs[khq] < (unsigned)t) { __nanosleep(32); }
            }
            mbar_expect_tx(my_bar, 32768u);
            bulk_g2s(hs_dst0 + (unsigned)khq * 32768u,
                     (const char*)g_h[cur] + (unsigned)khq * 32768u,
                     32768u, my_bar);
        }

        // ---- wait only for this warp's k-quarter
        mbar_wait(my_bar, (unsigned)(t & 1));

        // ---- compute: 128 k x (2 hl rows x 2 gate-pairs x 2 batches)
        float2 A000 = make_float2(0.f, 0.f), A001 = A000, A010 = A000, A011 = A000;
        float2 A100 = A000, A101 = A000, A110 = A000, A111 = A000;

        const float* wP = Wsp + (khq * 128) * 16 + 8 * hlh;
        const float* hP = hs + (khq * 128) * 64 + 2 * bp;

        #pragma unroll 4
        for (int kl = 0; kl < 128; kl++) {
            const float4 w4a = *(const float4*)(wP);       // rows: hl=2hlh, gates 0..3
            const float4 w4b = *(const float4*)(wP + 4);   // rows: hl=2hlh+1
            const float2 hv  = *(const float2*)(hP);
            const float2 d0 = make_float2(hv.x, hv.x);
            const float2 d1 = make_float2(hv.y, hv.y);
            const float2 w01a = make_float2(w4a.x, w4a.y);
            const float2 w23a = make_float2(w4a.z, w4a.w);
            const float2 w01b = make_float2(w4b.x, w4b.y);
            const float2 w23b = make_float2(w4b.z, w4b.w);
            A000 = ffma2(w01a, d0, A000);
            A001 = ffma2(w01a, d1, A001);
            A010 = ffma2(w23a, d0, A010);
            A011 = ffma2(w23a, d1, A011);
            A100 = ffma2(w01b, d0, A100);
            A101 = ffma2(w01b, d1, A101);
            A110 = ffma2(w23b, d0, A110);
            A111 = ffma2(w23b, d1, A111);
            wP += 16;
            hP += 64;
        }

        // ---- scatter partials: red[((khq*4+hl)*2+gp)*64 + b] (f2 = gate pair)
        {
            const int hlA = 2 * hlh, hlB = 2 * hlh + 1;
            float4* r0 = (float4*)(red + ((khq * 4 + hlA) * 2 + 0) * 64 + 2 * bp);
            float4* r1 = (float4*)(red + ((khq * 4 + hlA) * 2 + 1) * 64 + 2 * bp);
            float4* r2 = (float4*)(red + ((khq * 4 + hlB) * 2 + 0) * 64 + 2 * bp);
            float4* r3 = (float4*)(red + ((khq * 4 + hlB) * 2 + 1) * 64 + 2 * bp);
            *r0 = make_float4(A000.x, A000.y, A001.x, A001.y);
            *r1 = make_float4(A010.x, A010.y, A011.x, A011.y);
            *r2 = make_float4(A100.x, A100.y, A101.x, A101.y);
            *r3 = make_float4(A110.x, A110.y, A111.x, A111.y);
        }
        __syncthreads();

        // ---- reduce 4 k-quarters + gates + release (epi threads only)
        if (epi) {
            float2 s01_0 = make_float2(0.f, 0.f), s01_1 = s01_0;
            float2 s23_0 = s01_0, s23_1 = s01_0;
            #pragma unroll
            for (int q = 0; q < 4; q++) {
                const float4 v01 = *(const float4*)(red + ((q * 4 + ehl) * 2 + 0) * 64 + 2 * ebp);
                const float4 v23 = *(const float4*)(red + ((q * 4 + ehl) * 2 + 1) * 64 + 2 * ebp);
                s01_0 = fadd2(s01_0, make_float2(v01.x, v01.y));
                s01_1 = fadd2(s01_1, make_float2(v01.z, v01.w));
                s23_0 = fadd2(s23_0, make_float2(v23.x, v23.y));
                s23_1 = fadd2(s23_1, make_float2(v23.z, v23.w));
            }
            // s01 = (f, i), s23 = (o, c); gx already contains bx + bh
            const float pf0 = s01_0.x + gxf.x, pf1 = s01_1.x + gxf.y;
            const float pi0 = s01_0.y + gxi.x, pi1 = s01_1.y + gxi.y;
            const float po0 = s23_0.x + gxo.x, po1 = s23_1.x + gxo.y;
            const float pc0 = s23_0.y + gxc.x, pc1 = s23_1.y + gxc.y;

            const float f0 = fast_sigmoid(pf0), f1 = fast_sigmoid(pf1);
            const float i0 = fast_sigmoid(pi0), i1 = fast_sigmoid(pi1);
            const float o0 = fast_sigmoid(po0), o1 = fast_sigmoid(po1);
            const float q0 = fast_tanh(pc0),    q1 = fast_tanh(pc1);

            c0 = f0 * c0 + i0 * q0;
            c1 = f1 * c1 + i1 * q1;
            const float hn0 = o0 * fast_tanh(c0);
            const float hn1 = o1 * fast_tanh(c1);

            // publish next-step h first (only thing other CTAs wait on)
            __stcg((float2*)(g_h[cur ^ 1] + eh * BATCH + 2 * ebp),
                   make_float2(hn0, hn1));

            // epi-only named barrier (warps 0-3, 128 threads), then release
            asm volatile("bar.sync 1, 128;" ::: "memory");
            if (tid == 0) {
                __threadfence();
                unsigned old = atomicAdd(&g_bars[gid], 1u);
                if (old == (unsigned)t * 32u + 31u) {
                    g_epochs[gid] = (unsigned)(t + 1);
                }
            }

            // off-critical-path outputs
            float* so = h_seq + ((size_t)t * BATCH + 2 * ebp) * HID + eh;
            so[0]   = hn0;
            so[HID] = hn1;
            if (t == T_LEN - 1) {
                out_hlast[(size_t)(2 * ebp) * HID + eh]     = hn0;
                out_hlast[(size_t)(2 * ebp + 1) * HID + eh] = hn1;
                out_clast[(size_t)(2 * ebp) * HID + eh]     = c0;
                out_clast[(size_t)(2 * ebp + 1) * HID + eh] = c1;
            }
        }

        cur ^= 1;
    }
}

// ---------------- launch ----------------
extern "C" void kernel_launch(void* const* d_in, const int* in_sizes, int n_in,
                              void* d_out, int out_size) {
    const float* x  = (const float*)d_in[0];
    const float* Wx = (const float*)d_in[1];
    const float* bx = (const float*)d_in[2];
    const float* Wh = (const float*)d_in[3];
    const float* bh = (const float*)d_in[4];

    float* out       = (float*)d_out;
    float* out_hlast = out + (size_t)T_LEN * BATCH * HID;
    float* out_clast = out_hlast + (size_t)BATCH * HID;

    const int gx_smem = (256 * 65 + 32 * 256) * sizeof(float);   // 99328 B
    const int ps_smem = (8192 + 32768 + 4096 + 16) * sizeof(float); // 180288 B
    cudaFuncSetAttribute(gx_kernel,       cudaFuncAttributeMaxDynamicSharedMemorySize, gx_smem);
    cudaFuncSetAttribute(lstm_persistent, cudaFuncAttributeMaxDynamicSharedMemorySize, ps_smem);

    init_state_kernel<<<128, 512>>>();
    gx_kernel<<<dim3(64, 512), 256, gx_smem>>>(x, Wx, bx, bh);
    lstm_persistent<<<NCTA, 256, ps_smem>>>(Wh, out, out_hlast, out_clast);
}